// round 3
// baseline (speedup 1.0000x reference)
#include <cuda_runtime.h>
#include <cstdint>

#define NCTA 128
#define NTHR 256

constexpr int B = 64, T = 1024, D = 256, H = 256;
constexpr int P = 16;              // CTAs per cluster (column partition)
constexpr int BG = 8;              // batches per cluster
constexpr int CPC = H / P;         // 16 hidden columns per CTA

// ---------------- PTX helpers ----------------
__device__ __forceinline__ uint32_t smem_u32(const void* p) {
    uint32_t a;
    asm("{ .reg .u64 t; cvta.to.shared.u64 t, %1; cvt.u32.u64 %0, t; }"
        : "=r"(a) : "l"(p));
    return a;
}
__device__ __forceinline__ uint32_t mapa_rank(uint32_t addr, int rank) {
    uint32_t r;
    asm("mapa.shared::cluster.u32 %0, %1, %2;" : "=r"(r) : "r"(addr), "r"(rank));
    return r;
}
__device__ __forceinline__ void st_cluster_v2(uint32_t addr, float a, float b) {
    asm volatile("st.shared::cluster.v2.f32 [%0], {%1,%2};"
                 :: "r"(addr), "f"(a), "f"(b) : "memory");
}
__device__ __forceinline__ void mbar_init(uint32_t addr, uint32_t cnt) {
    asm volatile("mbarrier.init.shared.b64 [%0], %1;" :: "r"(addr), "r"(cnt) : "memory");
}
__device__ __forceinline__ void mbar_arrive_remote(uint32_t mapped_addr) {
    asm volatile("mbarrier.arrive.release.cluster.shared::cluster.b64 _, [%0];"
                 :: "r"(mapped_addr) : "memory");
}
__device__ __forceinline__ void mbar_wait(uint32_t addr, uint32_t parity) {
    uint32_t done;
    asm volatile(
        "{\n\t.reg .pred p;\n\t"
        "mbarrier.try_wait.parity.acquire.cluster.shared::cta.b64 p, [%1], %2;\n\t"
        "selp.b32 %0, 1, 0, p;\n\t}"
        : "=r"(done) : "r"(addr), "r"(parity) : "memory");
    if (!done) {
        asm volatile(
            "{\n\t.reg .pred P1;\n\t"
            "W%=:\n\t"
            "mbarrier.try_wait.parity.acquire.cluster.shared::cta.b64 P1, [%0], %1, 0x989680;\n\t"
            "@P1 bra.uni D%=;\n\t"
            "bra.uni W%=;\n\t"
            "D%=:\n\t}"
            :: "r"(addr), "r"(parity) : "memory");
    }
}
__device__ __forceinline__ float sigmoidf_(float x) {
    return 1.0f / (1.0f + __expf(-x));
}

__global__ void __launch_bounds__(NTHR, 1) rgru_kernel(
    const float* __restrict__ x, const float* __restrict__ h0,
    const float* __restrict__ eps,
    const float* __restrict__ Wz, const float* __restrict__ bz,
    const float* __restrict__ Wr, const float* __restrict__ br,
    const float* __restrict__ Wtx, const float* __restrict__ btx,
    const float* __restrict__ Wth, const float* __restrict__ bth,
    const float* __restrict__ Wd, const float* __restrict__ bd,
    float* __restrict__ out)
{
    __shared__ float xh_s[BG][512];     // [b][ x(0:256) | h(256:512) ]
    __shared__ float hb_s[BG][256];     // h_base, full row per batch
    __shared__ float eps_s[BG][CPC];    // eps slice for this CTA's columns
    __shared__ __align__(8) unsigned long long bar_hb, bar_sm;

    const int tid = threadIdx.x;
    const int l = tid & 31;
    const int w = tid >> 5;            // warp 0..7, owns 2 columns
    const int g = blockIdx.x >> 4;     // cluster id (batch group)
    const int p = blockIdx.x & 15;     // cluster rank
    const int Jb = p * CPC;
    const int Bb = g * BG;
    const int j0 = Jb + 2 * w;         // warp's two global columns

    // ---------------- weights into registers (once) ----------------
    float wz[2][16], wr[2][16], wu[2][8], wv[2][8], wm[2][8], wlv[2][8];
    float bzc[2], brc[2], btxc[2], bthc[2], bmc[2], blc[2];
#pragma unroll
    for (int c = 0; c < 2; c++) {
        int j = j0 + c;
#pragma unroll
        for (int q = 0; q < 4; q++)
#pragma unroll
            for (int i = 0; i < 4; i++) {
                int k = 128 * q + 4 * l + i;
                wz[c][4 * q + i] = Wz[k * H + j];
                wr[c][4 * q + i] = Wr[k * H + j];
            }
#pragma unroll
        for (int q = 0; q < 2; q++)
#pragma unroll
            for (int i = 0; i < 4; i++) {
                int k = 128 * q + 4 * l + i;
                wu[c][4 * q + i]  = Wtx[k * H + j];
                wv[c][4 * q + i]  = Wth[k * H + j];
                wm[c][4 * q + i]  = Wd[k * (2 * H) + j];
                wlv[c][4 * q + i] = Wd[k * (2 * H) + j + H];
            }
        bzc[c] = bz[j]; brc[c] = br[j]; btxc[c] = btx[j]; bthc[c] = bth[j];
        bmc[c] = bd[j]; blc[c] = bd[j + H];
    }

    const uint32_t bar_hb_a = smem_u32(&bar_hb);
    const uint32_t bar_sm_a = smem_u32(&bar_sm);
    if (tid == 0) { mbar_init(bar_hb_a, P); mbar_init(bar_sm_a, P); }

    // peer push addresses (lanes 0..15 each own one destination rank)
    uint32_t peer_hb = 0, peer_xh = 0, peer_bhb = 0, peer_bsm = 0;
    if (l < 16) {
        peer_hb = mapa_rank(smem_u32(&hb_s[0][j0]), l);
        peer_xh = mapa_rank(smem_u32(&xh_s[0][256 + j0]), l);
        if (w == 0) {
            peer_bhb = mapa_rank(bar_hb_a, l);
            peer_bsm = mapa_rank(bar_sm_a, l);
        }
    }
    __syncthreads();                       // barrier init visible CTA-wide
    asm volatile("barrier.cluster.arrive.aligned;" ::: "memory");

    // ---------------- initial staging: x(0), h0 (local) ----------------
    for (int f = tid; f < BG * 64; f += NTHR) {
        int b = f >> 6, q = f & 63;
        ((float4*)xh_s[b])[q] = ((const float4*)(x + ((Bb + b) * T) * D))[q];
    }
    for (int f = tid; f < BG * 64; f += NTHR) {
        int b = f >> 6, q = f & 63;
        ((float4*)(xh_s[b] + 256))[q] = ((const float4*)(h0 + (Bb + b) * H))[q];
    }
    asm volatile("barrier.cluster.wait.aligned;" ::: "memory");  // peers' mbar init done
    __syncthreads();

    for (int t = 0; t < T; t++) {
        const unsigned ph = (unsigned)(t & 1);

        // prefetch eps(t) for this CTA's columns (consumed in phase 2)
        if (tid < 32) {
            int b = l >> 2, q = l & 3;
            ((float4*)eps_s[b])[q] =
                __ldg((const float4*)(eps + ((Bb + b) * T + t) * H + Jb) + q);
        }

        // ================= phase 1: z, r, htil -> h_base =================
#pragma unroll 2
        for (int b = 0; b < BG; b++) {
            const float4* row = (const float4*)xh_s[b];
            float4 t0 = row[l], t1 = row[32 + l], t2 = row[64 + l], t3 = row[96 + l];
            float a[16] = { t0.x, t0.y, t0.z, t0.w,  t1.x, t1.y, t1.z, t1.w,
                            t2.x, t2.y, t2.z, t2.w,  t3.x, t3.y, t3.z, t3.w };
            float hbv[2];
#pragma unroll
            for (int c = 0; c < 2; c++) {
                float sz = 0.f, sr = 0.f, su = 0.f, sv = 0.f;
#pragma unroll
                for (int i = 0; i < 16; i++) {
                    sz = fmaf(wz[c][i], a[i], sz);
                    sr = fmaf(wr[c][i], a[i], sr);
                }
#pragma unroll
                for (int i = 0; i < 8; i++) {
                    su = fmaf(wu[c][i], a[i], su);      // x part (k < 256)
                    sv = fmaf(wv[c][i], a[8 + i], sv);  // h part (k >= 256)
                }
#pragma unroll
                for (int off = 16; off; off >>= 1) {
                    sz += __shfl_xor_sync(0xffffffffu, sz, off);
                    sr += __shfl_xor_sync(0xffffffffu, sr, off);
                    su += __shfl_xor_sync(0xffffffffu, su, off);
                    sv += __shfl_xor_sync(0xffffffffu, sv, off);
                }
                // butterfly leaves sums in ALL lanes
                float z = sigmoidf_(sz + bzc[c]);
                float r = sigmoidf_(sr + brc[c]);
                float htil = tanhf(su + btxc[c] + r * (sv + bthc[c]));
                float hp = xh_s[b][256 + j0 + c];
                hbv[c] = z * hp + (1.0f - z) * htil;
            }
            if (l < 16)   // lane r pushes this warp's 2 columns into rank r's hb_s
                st_cluster_v2(peer_hb + (uint32_t)(b * 256 * 4), hbv[0], hbv[1]);
        }
        __syncthreads();
        if (w == 0 && l < 16) mbar_arrive_remote(peer_bhb);

        // overlap: stage x(t+1) into the (dead) x-half while waiting
        if (t + 1 < T) {
            for (int f = tid; f < BG * 64; f += NTHR) {
                int b = f >> 6, q = f & 63;
                ((float4*)xh_s[b])[q] =
                    __ldg((const float4*)(x + ((Bb + b) * T + t + 1) * D) + q);
            }
        }

        mbar_wait(bar_hb_a, ph);   // h_base fully gathered in local hb_s

        // ================= phase 2: params -> sample =================
#pragma unroll 2
        for (int b = 0; b < BG; b++) {
            const float4* hrow = (const float4*)hb_s[b];
            float4 c0 = hrow[l], c1 = hrow[32 + l];
            float hv[8] = { c0.x, c0.y, c0.z, c0.w,  c1.x, c1.y, c1.z, c1.w };
            float sva[2];
#pragma unroll
            for (int c = 0; c < 2; c++) {
                float sm = 0.f, sl = 0.f;
#pragma unroll
                for (int i = 0; i < 8; i++) {
                    sm = fmaf(wm[c][i], hv[i], sm);
                    sl = fmaf(wlv[c][i], hv[i], sl);
                }
#pragma unroll
                for (int off = 16; off; off >>= 1) {
                    sm += __shfl_xor_sync(0xffffffffu, sm, off);
                    sl += __shfl_xor_sync(0xffffffffu, sl, off);
                }
                float mean = fminf(fmaxf(sm + bmc[c], -1000.0f), 1000.0f);
                float lv   = fminf(fmaxf(sl + blc[c], -30.0f), 30.0f);
                sva[c] = fmaf(__expf(0.5f * lv), eps_s[b][2 * w + c], mean);
            }
            if (l < 16)   // push sample into every rank's h-half for step t+1
                st_cluster_v2(peer_xh + (uint32_t)(b * 512 * 4), sva[0], sva[1]);
            if (l == 0) { // fire-and-forget global output (off critical path)
                float2 o = make_float2(sva[0], sva[1]);
                *(float2*)(out + ((size_t)(Bb + b) * T + t) * H + j0) = o;
                if (t == T - 1)
                    *(float2*)(out + (size_t)B * T * H + (Bb + b) * H + j0) = o;
            }
        }
        __syncthreads();
        if (w == 0 && l < 16) mbar_arrive_remote(peer_bsm);
        mbar_wait(bar_sm_a, ph);   // h(t+1) fully gathered in local xh_s
    }
}

extern "C" void kernel_launch(void* const* d_in, const int* in_sizes, int n_in,
                              void* d_out, int out_size) {
    const float* x   = (const float*)d_in[0];
    const float* h0  = (const float*)d_in[1];
    const float* eps = (const float*)d_in[2];
    const float* Wz  = (const float*)d_in[3];
    const float* bz  = (const float*)d_in[4];
    const float* Wr  = (const float*)d_in[5];
    const float* br  = (const float*)d_in[6];
    const float* Wtx = (const float*)d_in[7];
    const float* btx = (const float*)d_in[8];
    const float* Wth = (const float*)d_in[9];
    const float* bth = (const float*)d_in[10];
    const float* Wd  = (const float*)d_in[11];
    const float* bd  = (const float*)d_in[12];
    float* out = (float*)d_out;

    cudaFuncSetAttribute(rgru_kernel,
                         cudaFuncAttributeNonPortableClusterSizeAllowed, 1);

    cudaLaunchConfig_t cfg = {};
    cfg.gridDim  = dim3(NCTA, 1, 1);
    cfg.blockDim = dim3(NTHR, 1, 1);
    cfg.dynamicSmemBytes = 0;
    cfg.stream = 0;
    cudaLaunchAttribute attrs[1];
    attrs[0].id = cudaLaunchAttributeClusterDimension;
    attrs[0].val.clusterDim.x = P;
    attrs[0].val.clusterDim.y = 1;
    attrs[0].val.clusterDim.z = 1;
    cfg.attrs = attrs;
    cfg.numAttrs = 1;

    cudaLaunchKernelEx(&cfg, rgru_kernel, x, h0, eps, Wz, bz, Wr, br,
                       Wtx, btx, Wth, bth, Wd, bd, out);
}

// round 4
// speedup vs baseline: 1.5351x; 1.5351x over previous
#include <cuda_runtime.h>
#include <cstdint>

#define NCTA 128
#define NTHR 256

constexpr int B = 64, T = 1024, D = 256, H = 256;
constexpr int GROUPS = 8;
constexpr int P = 16;              // CTAs per group
constexpr int BG = 8;              // batches per group
constexpr int CPC = 16;            // columns per CTA

__device__ unsigned g_arr[GROUPS][4][32];
__device__ unsigned g_genv[GROUPS][4][32];
__device__ float g_hb[B * H];

// ---------------- helpers ----------------
__device__ __forceinline__ uint64_t packf2(float lo, float hi) {
    uint64_t d; asm("mov.b64 %0, {%1, %2};" : "=l"(d) : "f"(lo), "f"(hi)); return d;
}
__device__ __forceinline__ float2 unpackf2(uint64_t v) {
    float2 r; asm("mov.b64 {%0, %1}, %2;" : "=f"(r.x), "=f"(r.y) : "l"(v)); return r;
}
__device__ __forceinline__ uint64_t fma2(uint64_t a, uint64_t b, uint64_t c) {
    uint64_t d;
    asm("fma.rn.f32x2 %0, %1, %2, %3;" : "=l"(d) : "l"(a), "l"(b), "l"(c));
    return d;
}
__device__ __forceinline__ float sigmoid_fast(float x) {
    return __fdividef(1.0f, 1.0f + __expf(-x));
}
__device__ __forceinline__ float tanh_fast(float x) {
    float e = __expf(2.0f * x);
    return 1.0f - __fdividef(2.0f, e + 1.0f);
}
__device__ __forceinline__ void arrive_bar(int g, int id, unsigned tgt) {
    unsigned a = atomicAdd(&g_arr[g][id][0], 1u);
    if (a == (unsigned)(P - 1)) {
        g_arr[g][id][0] = 0u;
        __threadfence();
        atomicExch(&g_genv[g][id][0], tgt);
    }
}
__device__ __forceinline__ void waitgen(int g, int id, unsigned tgt) {
    volatile unsigned* p = &g_genv[g][id][0];
    while ((int)(*p - tgt) < 0) { }
    __threadfence();
}

__global__ void __launch_bounds__(NTHR, 1) rgru_kernel(
    const float* __restrict__ x, const float* __restrict__ h0,
    const float* __restrict__ eps,
    const float* __restrict__ Wz, const float* __restrict__ bz,
    const float* __restrict__ Wr, const float* __restrict__ br,
    const float* __restrict__ Wtx, const float* __restrict__ btx,
    const float* __restrict__ Wth, const float* __restrict__ bth,
    const float* __restrict__ Wd, const float* __restrict__ bd,
    float* __restrict__ out)
{
    __shared__ __align__(16) float xh_s[BG][512];   // [b][ x | h ]
    __shared__ __align__(16) float hb_s[BG][256];
    __shared__ float eps_s[BG][CPC];
    __shared__ unsigned sb[4];

    const int tid = threadIdx.x;
    const int l = tid & 31;
    const int w = tid >> 5;            // warp 0..7 -> 2 columns
    const int g = blockIdx.x >> 4;
    const int p = blockIdx.x & 15;
    const int Jb = p * CPC;
    const int Bb = g * BG;
    const int j0 = Jb + 2 * w;

    // ---------------- packed weights into registers ----------------
    uint64_t wz2[2][8], wr2[2][8], wu2[2][4], wv2[2][4], wm2[2][4], wlv2[2][4];
#pragma unroll
    for (int c = 0; c < 2; c++) {
        int j = j0 + c;
#pragma unroll
        for (int q = 0; q < 4; q++)
#pragma unroll
            for (int i = 0; i < 2; i++) {
                int k0 = 128 * q + 4 * l + 2 * i;
                wz2[c][2 * q + i] = packf2(Wz[k0 * H + j], Wz[(k0 + 1) * H + j]);
                wr2[c][2 * q + i] = packf2(Wr[k0 * H + j], Wr[(k0 + 1) * H + j]);
            }
#pragma unroll
        for (int q = 0; q < 2; q++)
#pragma unroll
            for (int i = 0; i < 2; i++) {
                int k0 = 128 * q + 4 * l + 2 * i;
                wu2[c][2 * q + i]  = packf2(Wtx[k0 * H + j], Wtx[(k0 + 1) * H + j]);
                wv2[c][2 * q + i]  = packf2(Wth[k0 * H + j], Wth[(k0 + 1) * H + j]);
                wm2[c][2 * q + i]  = packf2(Wd[k0 * 2 * H + j], Wd[(k0 + 1) * 2 * H + j]);
                wlv2[c][2 * q + i] = packf2(Wd[k0 * 2 * H + j + H], Wd[(k0 + 1) * 2 * H + j + H]);
            }
    }
    // per-task-lane biases: task k = (bb = k>>1, c = k&1); lane k handles task k
    const int lc = l & 1;
    const float bzl  = bz[j0 + lc],  brl = br[j0 + lc];
    const float btxl = btx[j0 + lc], bthl = bth[j0 + lc];
    const float bml  = bd[j0 + lc],  bll = bd[j0 + lc + H];

    if (tid < 4) sb[tid] = *(volatile unsigned*)&g_genv[g][tid][0];
    __syncthreads();
    const unsigned sb0 = sb[0], sb1 = sb[1], sb2 = sb[2], sb3 = sb[3];

    // ---------------- staging lambdas ----------------
    auto stage_x_all = [&](int t1) {
#pragma unroll
        for (int rr = 0; rr < 2; rr++) {
            int f = tid + rr * NTHR;
            int b = f >> 6, q = f & 63;
            ((float4*)xh_s[b])[q] =
                __ldg((const float4*)(x + ((size_t)(Bb + b) * T + t1) * D) + q);
        }
    };
    auto stage_h_half = [&](int tsrc, int bbase) {   // h from out row tsrc
        int b = bbase + (tid >> 6), q = tid & 63;
        ((float4*)(xh_s[b] + 256))[q] =
            __ldcg((const float4*)(out + ((size_t)(Bb + b) * T + tsrc) * H) + q);
    };
    auto stage_hb_half = [&](int bbase) {
        int b = bbase + (tid >> 6), q = tid & 63;
        ((float4*)hb_s[b])[q] = __ldcg((const float4*)(g_hb + (Bb + b) * H) + q);
    };

    // ---------------- compute lambdas ----------------
    auto phase1 = [&](int bbase) {
        float tsz = 0.f, tsr = 0.f, tsu = 0.f, tsv = 0.f;
        const float hp = xh_s[bbase + ((l & 7) >> 1)][256 + j0 + lc];
#pragma unroll
        for (int bb = 0; bb < 4; bb++) {
            const ulonglong2* row = (const ulonglong2*)xh_s[bbase + bb];
            ulonglong2 p0 = row[l], p1 = row[32 + l], p2 = row[64 + l], p3 = row[96 + l];
            uint64_t a2[8] = { p0.x, p0.y, p1.x, p1.y, p2.x, p2.y, p3.x, p3.y };
#pragma unroll
            for (int c = 0; c < 2; c++) {
                uint64_t sz2 = 0, sr2 = 0, su2 = 0, sv2 = 0;
#pragma unroll
                for (int i = 0; i < 8; i++) {
                    sz2 = fma2(wz2[c][i], a2[i], sz2);
                    sr2 = fma2(wr2[c][i], a2[i], sr2);
                }
#pragma unroll
                for (int i = 0; i < 4; i++) {
                    su2 = fma2(wu2[c][i], a2[i], su2);
                    sv2 = fma2(wv2[c][i], a2[4 + i], sv2);
                }
                float2 f;
                f = unpackf2(sz2); float sz = f.x + f.y;
                f = unpackf2(sr2); float sr = f.x + f.y;
                f = unpackf2(su2); float su = f.x + f.y;
                f = unpackf2(sv2); float sv = f.x + f.y;
#pragma unroll
                for (int off = 16; off; off >>= 1) {
                    sz += __shfl_xor_sync(0xffffffffu, sz, off);
                    sr += __shfl_xor_sync(0xffffffffu, sr, off);
                    su += __shfl_xor_sync(0xffffffffu, su, off);
                    sv += __shfl_xor_sync(0xffffffffu, sv, off);
                }
                const int k = bb * 2 + c;
                tsz = (l == k) ? sz : tsz;
                tsr = (l == k) ? sr : tsr;
                tsu = (l == k) ? su : tsu;
                tsv = (l == k) ? sv : tsv;
            }
        }
        // one vectorized epilogue for 8 tasks (lanes 0..7)
        float z  = sigmoid_fast(tsz + bzl);
        float r  = sigmoid_fast(tsr + brl);
        float th = tanh_fast(tsu + btxl + r * (tsv + bthl));
        float hbv = fmaf(z, hp - th, th);   // z*hp + (1-z)*th
        if (l < 8)
            g_hb[(Bb + bbase + (l >> 1)) * H + j0 + lc] = hbv;
    };

    auto phase2 = [&](int bbase, int t) {
        float tsm = 0.f, tsl = 0.f;
#pragma unroll
        for (int bb = 0; bb < 4; bb++) {
            const ulonglong2* hrow = (const ulonglong2*)hb_s[bbase + bb];
            ulonglong2 q0 = hrow[l], q1 = hrow[32 + l];
            uint64_t h2[4] = { q0.x, q0.y, q1.x, q1.y };
#pragma unroll
            for (int c = 0; c < 2; c++) {
                uint64_t sm2 = 0, sl2 = 0;
#pragma unroll
                for (int i = 0; i < 4; i++) {
                    sm2 = fma2(wm2[c][i], h2[i], sm2);
                    sl2 = fma2(wlv2[c][i], h2[i], sl2);
                }
                float2 f;
                f = unpackf2(sm2); float sm = f.x + f.y;
                f = unpackf2(sl2); float sl = f.x + f.y;
#pragma unroll
                for (int off = 16; off; off >>= 1) {
                    sm += __shfl_xor_sync(0xffffffffu, sm, off);
                    sl += __shfl_xor_sync(0xffffffffu, sl, off);
                }
                const int k = bb * 2 + c;
                tsm = (l == k) ? sm : tsm;
                tsl = (l == k) ? sl : tsl;
            }
        }
        float mean = fminf(fmaxf(tsm + bml, -1000.0f), 1000.0f);
        float lv   = fminf(fmaxf(tsl + bll, -30.0f), 30.0f);
        float ep   = eps_s[bbase + ((l & 7) >> 1)][2 * w + lc];
        float s    = fmaf(__expf(0.5f * lv), ep, mean);
        if (l < 8) {
            int b = Bb + bbase + (l >> 1);
            out[((size_t)b * T + t) * H + j0 + lc] = s;
            if (t == T - 1) out[(size_t)B * T * H + b * H + j0 + lc] = s;
        }
    };

    // ---------------- prologue: stage x(0), h(0) ----------------
    stage_x_all(0);
#pragma unroll
    for (int rr = 0; rr < 2; rr++) {
        int f = tid + rr * NTHR;
        int b = f >> 6, q = f & 63;
        ((float4*)(xh_s[b] + 256))[q] = ((const float4*)(h0 + (Bb + b) * H))[q];
    }
    __syncthreads();

    // ---------------- main pipelined loop ----------------
    for (int t = 0; t < T; t++) {
        const unsigned tp1 = (unsigned)(t + 1);

        // eps(t) prefetch (consumed in phase2 this step)
        if (tid < 32) {
            int b = l >> 2, q = l & 3;
            ((float4*)eps_s[b])[q] =
                __ldg((const float4*)(eps + ((size_t)(Bb + b) * T + t) * H + Jb) + q);
        }

        // phase1 half0
        phase1(0);
        __threadfence(); __syncthreads();
        if (tid == 0) arrive_bar(g, 0, sb0 + tp1);

        // overlap bar2h1(t-1) wait + stage h(t) rows 4..7 under next work
        if (t > 0) {
            waitgen(g, 3, sb3 + (unsigned)t);
            stage_h_half(t - 1, 4);
        }
        __syncthreads();

        // phase1 half1
        phase1(4);
        __threadfence(); __syncthreads();
        if (tid == 0) arrive_bar(g, 1, sb1 + tp1);

        // wait h_base half0, stage, phase2 half0
        waitgen(g, 0, sb0 + tp1);
        stage_hb_half(0);
        __syncthreads();
        phase2(0, t);
        __threadfence(); __syncthreads();
        if (tid == 0) arrive_bar(g, 2, sb2 + tp1);

        // wait h_base half1, stage, phase2 half1
        waitgen(g, 1, sb1 + tp1);
        stage_hb_half(4);
        __syncthreads();
        phase2(4, t);
        __threadfence(); __syncthreads();
        if (tid == 0) arrive_bar(g, 3, sb3 + tp1);

        if (t + 1 < T) {
            stage_x_all(t + 1);               // x(t+1) into x-half (free now)
            waitgen(g, 2, sb2 + tp1);         // sample(t) half0 ready
            stage_h_half(t, 0);               // h(t+1) rows 0..3
            __syncthreads();
        }
    }
}

extern "C" void kernel_launch(void* const* d_in, const int* in_sizes, int n_in,
                              void* d_out, int out_size) {
    const float* x   = (const float*)d_in[0];
    const float* h0  = (const float*)d_in[1];
    const float* eps = (const float*)d_in[2];
    const float* Wz  = (const float*)d_in[3];
    const float* bz  = (const float*)d_in[4];
    const float* Wr  = (const float*)d_in[5];
    const float* br  = (const float*)d_in[6];
    const float* Wtx = (const float*)d_in[7];
    const float* btx = (const float*)d_in[8];
    const float* Wth = (const float*)d_in[9];
    const float* bth = (const float*)d_in[10];
    const float* Wd  = (const float*)d_in[11];
    const float* bd  = (const float*)d_in[12];
    float* out = (float*)d_out;

    rgru_kernel<<<NCTA, NTHR>>>(x, h0, eps, Wz, bz, Wr, br,
                                Wtx, btx, Wth, bth, Wd, bd, out);
}

// round 7
// speedup vs baseline: 1.5744x; 1.0256x over previous
#include <cuda_runtime.h>
#include <cstdint>

#define NCTA 128
#define NTHR 512

constexpr int B = 64, T = 1024, D = 256, H = 256;
constexpr int GROUPS = 8;
constexpr int P = 16;              // CTAs per group
constexpr int BG = 8;              // batches per group
constexpr int CPC = 16;            // columns per CTA (1 per warp)

__device__ unsigned g_arr[GROUPS][4][32];
__device__ unsigned g_genv[GROUPS][4][32];
__device__ unsigned g_abort = 0;
__device__ float g_hb[B * H];

// ---------------- helpers ----------------
__device__ __forceinline__ uint64_t packf2(float lo, float hi) {
    uint64_t d; asm("mov.b64 %0, {%1, %2};" : "=l"(d) : "f"(lo), "f"(hi)); return d;
}
__device__ __forceinline__ float2 unpackf2(uint64_t v) {
    float2 r; asm("mov.b64 {%0, %1}, %2;" : "=f"(r.x), "=f"(r.y) : "l"(v)); return r;
}
__device__ __forceinline__ uint64_t fma2(uint64_t a, uint64_t b, uint64_t c) {
    uint64_t d;
    asm("fma.rn.f32x2 %0, %1, %2, %3;" : "=l"(d) : "l"(a), "l"(b), "l"(c));
    return d;
}
__device__ __forceinline__ float sigmoid_fast(float x) {
    return __fdividef(1.0f, 1.0f + __expf(-x));
}
__device__ __forceinline__ float tanh_fast(float x) {
    float e = __expf(2.0f * x);
    return 1.0f - __fdividef(2.0f, e + 1.0f);
}
__device__ __forceinline__ void arrive_bar(int g, int id, unsigned tgt) {
    unsigned a = atomicAdd(&g_arr[g][id][0], 1u);
    if (a == (unsigned)(P - 1)) {
        g_arr[g][id][0] = 0u;
        __threadfence();
        atomicExch(&g_genv[g][id][0], tgt);
    }
}
// Bounded spin: aborts (sets g_abort) after ~1e9 cycles so the kernel can
// NEVER hang the GPU. Normal waits are <10us; 1e9 cyc ~ 0.5s.
__device__ __forceinline__ void waitgen(int g, int id, unsigned tgt) {
    volatile unsigned* p = &g_genv[g][id][0];
    if ((int)(*p - tgt) < 0) {
        long long t0 = clock64();
        while ((int)(*p - tgt) < 0) {
            if (*(volatile unsigned*)&g_abort) return;
            if (clock64() - t0 > 1000000000LL) { atomicExch(&g_abort, 1u); return; }
            __nanosleep(20);
        }
    }
    __threadfence();
}

__global__ void __launch_bounds__(NTHR, 1) rgru_kernel(
    const float* __restrict__ x, const float* __restrict__ h0,
    const float* __restrict__ eps,
    const float* __restrict__ Wz, const float* __restrict__ bz,
    const float* __restrict__ Wr, const float* __restrict__ br,
    const float* __restrict__ Wtx, const float* __restrict__ btx,
    const float* __restrict__ Wth, const float* __restrict__ bth,
    const float* __restrict__ Wd, const float* __restrict__ bd,
    float* __restrict__ out)
{
    __shared__ __align__(16) float x_s[BG][256];
    __shared__ float eps_s[BG][CPC];
    __shared__ unsigned sb[4];

    const int tid = threadIdx.x;
    const int l = tid & 31;
    const int w = tid >> 5;            // warp 0..15 -> 1 column
    const int g = blockIdx.x >> 4;
    const int p = blockIdx.x & 15;
    const int Jb = p * CPC;
    const int Bb = g * BG;
    const int j = Jb + w;              // this warp's column

    // ---------------- packed weights into registers (once) ----------------
    uint64_t wz2[8], wr2[8], wu2[4], wv2[4], wm2[4], wlv2[4];
#pragma unroll
    for (int q = 0; q < 4; q++)
#pragma unroll
        for (int i = 0; i < 2; i++) {
            int k0 = 128 * q + 4 * l + 2 * i;
            wz2[2 * q + i] = packf2(Wz[k0 * H + j], Wz[(k0 + 1) * H + j]);
            wr2[2 * q + i] = packf2(Wr[k0 * H + j], Wr[(k0 + 1) * H + j]);
        }
#pragma unroll
    for (int q = 0; q < 2; q++)
#pragma unroll
        for (int i = 0; i < 2; i++) {
            int k0 = 128 * q + 4 * l + 2 * i;
            wu2[2 * q + i]  = packf2(Wtx[k0 * H + j], Wtx[(k0 + 1) * H + j]);
            wv2[2 * q + i]  = packf2(Wth[k0 * H + j], Wth[(k0 + 1) * H + j]);
            wm2[2 * q + i]  = packf2(Wd[k0 * 2 * H + j], Wd[(k0 + 1) * 2 * H + j]);
            wlv2[2 * q + i] = packf2(Wd[k0 * 2 * H + j + H], Wd[(k0 + 1) * 2 * H + j + H]);
        }
    const float bzj = bz[j], brj = br[j], btxj = btx[j], bthj = bth[j];
    const float bmj = bd[j], blj = bd[j + H];

    if (tid < 4) sb[tid] = *(volatile unsigned*)&g_genv[g][tid][0];
    __syncthreads();
    const unsigned sb0 = sb[0], sb1 = sb[1], sb2 = sb[2], sb3 = sb[3];

    auto stage_x = [&](int t1) {
        int b = tid >> 6, q = tid & 63;
        ((float4*)x_s[b])[q] =
            __ldg((const float4*)(x + ((size_t)(Bb + b) * T + t1) * D) + q);
    };

    // phase 1: z, r, htil -> g_hb   (half = 4 batches starting at bbase)
    auto phase1 = [&](int bbase, int t) {
        float fin = 0.f;
        const int pb = Bb + bbase + (l & 3);
        const float* hrow_t = (t == 0) ? (h0 + pb * H)
                                       : (out + ((size_t)pb * T + (t - 1)) * H);
        float hpsel = __ldcg(hrow_t + j);
#pragma unroll
        for (int bb = 0; bb < 4; bb++) {
            const int b = Bb + bbase + bb;
            const float* xrow = x_s[bbase + bb];
            const float* hrow = (t == 0) ? (h0 + b * H)
                                         : (out + ((size_t)b * T + (t - 1)) * H);
            ulonglong2 p0 = ((const ulonglong2*)xrow)[l];
            ulonglong2 p1 = ((const ulonglong2*)xrow)[32 + l];
            float4 hv0 = __ldcg((const float4*)hrow + l);
            float4 hv1 = __ldcg((const float4*)hrow + 32 + l);
            uint64_t a2[8] = { p0.x, p0.y, p1.x, p1.y,
                               packf2(hv0.x, hv0.y), packf2(hv0.z, hv0.w),
                               packf2(hv1.x, hv1.y), packf2(hv1.z, hv1.w) };
            uint64_t sz2 = 0, sr2 = 0, su2 = 0, sv2 = 0;
#pragma unroll
            for (int i = 0; i < 8; i++) {
                sz2 = fma2(wz2[i], a2[i], sz2);
                sr2 = fma2(wr2[i], a2[i], sr2);
            }
#pragma unroll
            for (int i = 0; i < 4; i++) {
                su2 = fma2(wu2[i], a2[i], su2);
                sv2 = fma2(wv2[i], a2[4 + i], sv2);
            }
            float2 f;
            f = unpackf2(sz2); float sz = f.x + f.y;
            f = unpackf2(sr2); float sr = f.x + f.y;
            f = unpackf2(su2); float su = f.x + f.y;
            f = unpackf2(sv2); float sv = f.x + f.y;
            // 6-shfl 4-value reduction: z->lanes0-7, r->8-15, u->16-23, v->24-31
            const bool hi16 = (l & 16) != 0;
            float sA = hi16 ? sz : su;
            float rA = __shfl_xor_sync(0xffffffffu, sA, 16);
            float zu = hi16 ? (su + rA) : (sz + rA);
            float sB = hi16 ? sr : sv;
            float rB = __shfl_xor_sync(0xffffffffu, sB, 16);
            float rv = hi16 ? (sv + rB) : (sr + rB);
            const bool hi8 = (l & 8) != 0;
            float sC = hi8 ? zu : rv;
            float rC = __shfl_xor_sync(0xffffffffu, sC, 8);
            float myv = hi8 ? (rv + rC) : (zu + rC);
            myv += __shfl_xor_sync(0xffffffffu, myv, 4);
            myv += __shfl_xor_sync(0xffffffffu, myv, 2);
            myv += __shfl_xor_sync(0xffffffffu, myv, 1);
            fin = ((l & 7) == bb) ? myv : fin;
        }
        const int tb = l & 3;
        float zs = __shfl_sync(0xffffffffu, fin, tb);
        float rs = __shfl_sync(0xffffffffu, fin, tb + 8);
        float us = __shfl_sync(0xffffffffu, fin, tb + 16);
        float vs = __shfl_sync(0xffffffffu, fin, tb + 24);
        float z  = sigmoid_fast(zs + bzj);
        float r  = sigmoid_fast(rs + brj);
        float th = tanh_fast(us + btxj + r * (vs + bthj));
        float hbv = fmaf(z, hpsel - th, th);         // z*hp + (1-z)*th
        if (l < 4) g_hb[(Bb + bbase + tb) * H + j] = hbv;
    };

    // phase 2: mean/log_var -> sample(out)
    auto phase2 = [&](int bbase, int t) {
        float fin = 0.f;
#pragma unroll
        for (int bb = 0; bb < 4; bb++) {
            const float* hbrow = g_hb + (Bb + bbase + bb) * H;
            float4 q0 = __ldcg((const float4*)hbrow + l);
            float4 q1 = __ldcg((const float4*)hbrow + 32 + l);
            uint64_t h2[4] = { packf2(q0.x, q0.y), packf2(q0.z, q0.w),
                               packf2(q1.x, q1.y), packf2(q1.z, q1.w) };
            uint64_t sm2 = 0, sl2 = 0;
#pragma unroll
            for (int i = 0; i < 4; i++) {
                sm2 = fma2(wm2[i], h2[i], sm2);
                sl2 = fma2(wlv2[i], h2[i], sl2);
            }
            float2 f;
            f = unpackf2(sm2); float sm = f.x + f.y;
            f = unpackf2(sl2); float sl = f.x + f.y;
            // 5-shfl 2-value reduction: m->lanes0-15, lv->16-31
            const bool hi16 = (l & 16) != 0;
            float sA = hi16 ? sm : sl;
            float rA = __shfl_xor_sync(0xffffffffu, sA, 16);
            float mv = hi16 ? (sl + rA) : (sm + rA);
            mv += __shfl_xor_sync(0xffffffffu, mv, 8);
            mv += __shfl_xor_sync(0xffffffffu, mv, 4);
            mv += __shfl_xor_sync(0xffffffffu, mv, 2);
            mv += __shfl_xor_sync(0xffffffffu, mv, 1);
            fin = ((l & 15) == bb) ? mv : fin;
        }
        const int tb = l & 3;
        float ms = __shfl_sync(0xffffffffu, fin, tb);
        float ls = __shfl_sync(0xffffffffu, fin, tb + 16);
        float mean = fminf(fmaxf(ms + bmj, -1000.0f), 1000.0f);
        float lv   = fminf(fmaxf(ls + blj, -30.0f), 30.0f);
        float s    = fmaf(__expf(0.5f * lv), eps_s[bbase + tb][w], mean);
        if (l < 4) {
            int b = Bb + bbase + tb;
            out[((size_t)b * T + t) * H + j] = s;
            if (t == T - 1) out[(size_t)B * T * H + b * H + j] = s;
        }
    };

    // ---------------- prologue ----------------
    stage_x(0);
    __syncthreads();

    // ---------------- main pipelined loop ----------------
    for (int t = 0; t < T; t++) {
        const unsigned tp1 = (unsigned)(t + 1);

        if (tid < 32) {   // eps(t) prefetch for this CTA's 16 columns
            int b = l >> 2, q = l & 3;
            ((float4*)eps_s[b])[q] =
                __ldg((const float4*)(eps + ((size_t)(Bb + b) * T + t) * H + Jb) + q);
        }

        phase1(0, t);
        __threadfence(); __syncthreads();
        if (tid == 0) arrive_bar(g, 0, sb0 + tp1);

        if (t > 0) {                       // out(t-1) rows 4..7 ready?
            if (tid == 0) waitgen(g, 3, sb3 + (unsigned)t);
            __syncthreads();
        }

        phase1(4, t);
        __threadfence(); __syncthreads();
        if (tid == 0) { arrive_bar(g, 1, sb1 + tp1); waitgen(g, 0, sb0 + tp1); }
        __syncthreads();

        phase2(0, t);
        __threadfence(); __syncthreads();
        if (tid == 0) { arrive_bar(g, 2, sb2 + tp1); waitgen(g, 1, sb1 + tp1); }
        __syncthreads();

        phase2(4, t);
        __threadfence(); __syncthreads();
        if (tid == 0) arrive_bar(g, 3, sb3 + tp1);

        if (t + 1 < T) {
            stage_x(t + 1);
            if (tid == 0) waitgen(g, 2, sb2 + tp1);  // out(t) rows 0..3 ready
            __syncthreads();
        }
    }
}

extern "C" void kernel_launch(void* const* d_in, const int* in_sizes, int n_in,
                              void* d_out, int out_size) {
    const float* x   = (const float*)d_in[0];
    const float* h0  = (const float*)d_in[1];
    const float* eps = (const float*)d_in[2];
    const float* Wz  = (const float*)d_in[3];
    const float* bz  = (const float*)d_in[4];
    const float* Wr  = (const float*)d_in[5];
    const float* br  = (const float*)d_in[6];
    const float* Wtx = (const float*)d_in[7];
    const float* btx = (const float*)d_in[8];
    const float* Wth = (const float*)d_in[9];
    const float* bth = (const float*)d_in[10];
    const float* Wd  = (const float*)d_in[11];
    const float* bd  = (const float*)d_in[12];
    float* out = (float*)d_out;

    rgru_kernel<<<NCTA, NTHR>>>(x, h0, eps, Wz, bz, Wr, br,
                                Wtx, btx, Wth, bth, Wd, bd, out);
}

// round 8
// speedup vs baseline: 1.5863x; 1.0075x over previous
#include <cuda_runtime.h>
#include <cstdint>

#define NCTA 128
#define NTHR 512

constexpr int B = 64, T = 1024, D = 256, H = 256;
constexpr int GROUPS = 8;
constexpr int P = 16;              // CTAs per group
constexpr int BG = 8;              // batches per group
constexpr int CPC = 16;            // columns per CTA (1 per warp)

__device__ unsigned g_arr[GROUPS][4][32];   // monotonic CTA-arrival counters
__device__ unsigned g_genv[GROUPS][4][32];  // generation words
__device__ unsigned g_abort = 0;
__device__ float g_hb[B * H];

// ---------------- helpers ----------------
__device__ __forceinline__ uint64_t packf2(float lo, float hi) {
    uint64_t d; asm("mov.b64 %0, {%1, %2};" : "=l"(d) : "f"(lo), "f"(hi)); return d;
}
__device__ __forceinline__ float2 unpackf2(uint64_t v) {
    float2 r; asm("mov.b64 {%0, %1}, %2;" : "=f"(r.x), "=f"(r.y) : "l"(v)); return r;
}
__device__ __forceinline__ uint64_t fma2(uint64_t a, uint64_t b, uint64_t c) {
    uint64_t d;
    asm("fma.rn.f32x2 %0, %1, %2, %3;" : "=l"(d) : "l"(a), "l"(b), "l"(c));
    return d;
}
__device__ __forceinline__ float sigmoid_fast(float x) {
    return __fdividef(1.0f, 1.0f + __expf(-x));
}
__device__ __forceinline__ float tanh_fast(float x) {
    float e = __expf(2.0f * x);
    return 1.0f - __fdividef(2.0f, e + 1.0f);
}

__global__ void __launch_bounds__(NTHR, 1) rgru_kernel(
    const float* __restrict__ x, const float* __restrict__ h0,
    const float* __restrict__ eps,
    const float* __restrict__ Wz, const float* __restrict__ bz,
    const float* __restrict__ Wr, const float* __restrict__ br,
    const float* __restrict__ Wtx, const float* __restrict__ btx,
    const float* __restrict__ Wth, const float* __restrict__ bth,
    const float* __restrict__ Wd, const float* __restrict__ bd,
    float* __restrict__ out)
{
    __shared__ unsigned swc[4];   // per-CTA warp-arrival counters (monotonic)
    __shared__ unsigned sbs[4];   // generation snapshot

    const int tid = threadIdx.x;
    const int l = tid & 31;
    const int w = tid >> 5;            // warp 0..15 -> 1 column
    const int g = blockIdx.x >> 4;
    const int p = blockIdx.x & 15;
    const int Jb = p * CPC;
    const int Bb = g * BG;
    const int j = Jb + w;              // this warp's column

    if (tid < 4) {
        swc[tid] = 0u;
        sbs[tid] = *(volatile unsigned*)&g_genv[g][tid][0];
    }
    __syncthreads();                   // the ONLY block-wide sync
    const unsigned sb0 = sbs[0], sb1 = sbs[1], sb2 = sbs[2], sb3 = sbs[3];

    // ---------------- packed weights into registers (once) ----------------
    uint64_t wz2[8], wr2[8], wu2[4], wv2[4], wm2[4], wlv2[4];
#pragma unroll
    for (int q = 0; q < 4; q++)
#pragma unroll
        for (int i = 0; i < 2; i++) {
            int k0 = 128 * q + 4 * l + 2 * i;
            wz2[2 * q + i] = packf2(Wz[k0 * H + j], Wz[(k0 + 1) * H + j]);
            wr2[2 * q + i] = packf2(Wr[k0 * H + j], Wr[(k0 + 1) * H + j]);
        }
#pragma unroll
    for (int q = 0; q < 2; q++)
#pragma unroll
        for (int i = 0; i < 2; i++) {
            int k0 = 128 * q + 4 * l + 2 * i;
            wu2[2 * q + i]  = packf2(Wtx[k0 * H + j], Wtx[(k0 + 1) * H + j]);
            wv2[2 * q + i]  = packf2(Wth[k0 * H + j], Wth[(k0 + 1) * H + j]);
            wm2[2 * q + i]  = packf2(Wd[k0 * 2 * H + j], Wd[(k0 + 1) * 2 * H + j]);
            wlv2[2 * q + i] = packf2(Wd[k0 * 2 * H + j + H], Wd[(k0 + 1) * 2 * H + j + H]);
        }
    const float bzj = bz[j], brj = br[j], btxj = btx[j], bthj = bth[j];
    const float bmj = bd[j], blj = bd[j + H];

    // per-warp hierarchical arrive: smem count -> CTA global count -> gen
    auto arrive = [&](int id, unsigned tgt) {
        __threadfence();
        if (l == 0) {
            unsigned o = atomicAdd(&swc[id], 1u);
            if (((o + 1u) & 15u) == 0u) {            // last warp of CTA
                unsigned go = atomicAdd(&g_arr[g][id][0], 1u);
                if (((go + 1u) % (unsigned)P) == 0u) // last CTA of group
                    atomicExch(&g_genv[g][id][0], tgt);
            }
        }
    };
    // per-warp tight poll (bounded: aborts after ~2e9 cyc so GPU can't hang)
    auto waitg = [&](int id, unsigned tgt) {
        volatile unsigned* pp = &g_genv[g][id][0];
        if ((int)(*pp - tgt) < 0) {
            long long t0 = clock64();
            while ((int)(*pp - tgt) < 0) {
                if (*(volatile unsigned*)&g_abort) return;
                if (clock64() - t0 > 2000000000LL) { atomicExch(&g_abort, 1u); return; }
            }
        }
        __threadfence();
    };

    // phase 1: z, r, htil -> g_hb   (half = 4 batches starting at bbase)
    auto phase1 = [&](int bbase, int t) {
        float fin = 0.f;
        const int pb = Bb + bbase + (l & 3);
        const float* hrow_t = (t == 0) ? (h0 + pb * H)
                                       : (out + ((size_t)pb * T + (t - 1)) * H);
        float hpsel = __ldcg(hrow_t + j);
#pragma unroll
        for (int bb = 0; bb < 4; bb++) {
            const int b = Bb + bbase + bb;
            const float* xrow = x + ((size_t)b * T + t) * D;
            const float* hrow = (t == 0) ? (h0 + b * H)
                                         : (out + ((size_t)b * T + (t - 1)) * H);
            float4 xv0 = __ldg((const float4*)xrow + l);
            float4 xv1 = __ldg((const float4*)xrow + 32 + l);
            float4 hv0 = __ldcg((const float4*)hrow + l);
            float4 hv1 = __ldcg((const float4*)hrow + 32 + l);
            uint64_t a2[8] = { packf2(xv0.x, xv0.y), packf2(xv0.z, xv0.w),
                               packf2(xv1.x, xv1.y), packf2(xv1.z, xv1.w),
                               packf2(hv0.x, hv0.y), packf2(hv0.z, hv0.w),
                               packf2(hv1.x, hv1.y), packf2(hv1.z, hv1.w) };
            uint64_t sz2 = 0, sr2 = 0, su2 = 0, sv2 = 0;
#pragma unroll
            for (int i = 0; i < 8; i++) {
                sz2 = fma2(wz2[i], a2[i], sz2);
                sr2 = fma2(wr2[i], a2[i], sr2);
            }
#pragma unroll
            for (int i = 0; i < 4; i++) {
                su2 = fma2(wu2[i], a2[i], su2);
                sv2 = fma2(wv2[i], a2[4 + i], sv2);
            }
            float2 f;
            f = unpackf2(sz2); float sz = f.x + f.y;
            f = unpackf2(sr2); float sr = f.x + f.y;
            f = unpackf2(su2); float su = f.x + f.y;
            f = unpackf2(sv2); float sv = f.x + f.y;
            // 6-shfl 4-value reduction: z->lanes0-7, r->8-15, u->16-23, v->24-31
            const bool hi16 = (l & 16) != 0;
            float sA = hi16 ? sz : su;
            float rA = __shfl_xor_sync(0xffffffffu, sA, 16);
            float zu = hi16 ? (su + rA) : (sz + rA);
            float sB = hi16 ? sr : sv;
            float rB = __shfl_xor_sync(0xffffffffu, sB, 16);
            float rv = hi16 ? (sv + rB) : (sr + rB);
            const bool hi8 = (l & 8) != 0;
            float sC = hi8 ? zu : rv;
            float rC = __shfl_xor_sync(0xffffffffu, sC, 8);
            float myv = hi8 ? (rv + rC) : (zu + rC);
            myv += __shfl_xor_sync(0xffffffffu, myv, 4);
            myv += __shfl_xor_sync(0xffffffffu, myv, 2);
            myv += __shfl_xor_sync(0xffffffffu, myv, 1);
            fin = ((l & 7) == bb) ? myv : fin;
        }
        const int tb = l & 3;
        float zs = __shfl_sync(0xffffffffu, fin, tb);
        float rs = __shfl_sync(0xffffffffu, fin, tb + 8);
        float us = __shfl_sync(0xffffffffu, fin, tb + 16);
        float vs = __shfl_sync(0xffffffffu, fin, tb + 24);
        float z  = sigmoid_fast(zs + bzj);
        float r  = sigmoid_fast(rs + brj);
        float th = tanh_fast(us + btxj + r * (vs + bthj));
        float hbv = fmaf(z, hpsel - th, th);         // z*hp + (1-z)*th
        if (l < 4) g_hb[(Bb + bbase + tb) * H + j] = hbv;
    };

    // phase 2: mean/log_var -> sample(out)
    auto phase2 = [&](int bbase, int t) {
        float fin = 0.f;
#pragma unroll
        for (int bb = 0; bb < 4; bb++) {
            const float* hbrow = g_hb + (Bb + bbase + bb) * H;
            float4 q0 = __ldcg((const float4*)hbrow + l);
            float4 q1 = __ldcg((const float4*)hbrow + 32 + l);
            uint64_t h2[4] = { packf2(q0.x, q0.y), packf2(q0.z, q0.w),
                               packf2(q1.x, q1.y), packf2(q1.z, q1.w) };
            uint64_t sm2 = 0, sl2 = 0;
#pragma unroll
            for (int i = 0; i < 4; i++) {
                sm2 = fma2(wm2[i], h2[i], sm2);
                sl2 = fma2(wlv2[i], h2[i], sl2);
            }
            float2 f;
            f = unpackf2(sm2); float sm = f.x + f.y;
            f = unpackf2(sl2); float sl = f.x + f.y;
            // 5-shfl 2-value reduction: m->lanes0-15, lv->16-31
            const bool hi16 = (l & 16) != 0;
            float sA = hi16 ? sm : sl;
            float rA = __shfl_xor_sync(0xffffffffu, sA, 16);
            float mv = hi16 ? (sl + rA) : (sm + rA);
            mv += __shfl_xor_sync(0xffffffffu, mv, 8);
            mv += __shfl_xor_sync(0xffffffffu, mv, 4);
            mv += __shfl_xor_sync(0xffffffffu, mv, 2);
            mv += __shfl_xor_sync(0xffffffffu, mv, 1);
            fin = ((l & 15) == bb) ? mv : fin;
        }
        const int tb = l & 3;
        float ms = __shfl_sync(0xffffffffu, fin, tb);
        float ls = __shfl_sync(0xffffffffu, fin, tb + 16);
        float mean = fminf(fmaxf(ms + bmj, -1000.0f), 1000.0f);
        float lv   = fminf(fmaxf(ls + blj, -30.0f), 30.0f);
        float ep   = __ldg(eps + ((size_t)(Bb + bbase + tb) * T + t) * H + j);
        float s    = fmaf(__expf(0.5f * lv), ep, mean);
        if (l < 4) {
            int b = Bb + bbase + tb;
            out[((size_t)b * T + t) * H + j] = s;
            if (t == T - 1) out[(size_t)B * T * H + b * H + j] = s;
        }
    };

    // ---------------- main loop: per-warp pipeline, no block syncs ----------
    for (int t = 0; t < T; t++) {
        const unsigned tp1 = (unsigned)(t + 1);

        if (t > 0) waitg(2, sb2 + (unsigned)t);   // out(t-1) rows 0..3 visible
        phase1(0, t);
        arrive(0, sb0 + tp1);

        if (t > 0) waitg(3, sb3 + (unsigned)t);   // out(t-1) rows 4..7 visible
        phase1(4, t);
        arrive(1, sb1 + tp1);

        waitg(0, sb0 + tp1);                      // h_base rows 0..3 visible
        phase2(0, t);
        arrive(2, sb2 + tp1);

        waitg(1, sb1 + tp1);                      // h_base rows 4..7 visible
        phase2(4, t);
        arrive(3, sb3 + tp1);
    }
}

extern "C" void kernel_launch(void* const* d_in, const int* in_sizes, int n_in,
                              void* d_out, int out_size) {
    const float* x   = (const float*)d_in[0];
    const float* h0  = (const float*)d_in[1];
    const float* eps = (const float*)d_in[2];
    const float* Wz  = (const float*)d_in[3];
    const float* bz  = (const float*)d_in[4];
    const float* Wr  = (const float*)d_in[5];
    const float* br  = (const float*)d_in[6];
    const float* Wtx = (const float*)d_in[7];
    const float* btx = (const float*)d_in[8];
    const float* Wth = (const float*)d_in[9];
    const float* bth = (const float*)d_in[10];
    const float* Wd  = (const float*)d_in[11];
    const float* bd  = (const float*)d_in[12];
    float* out = (float*)d_out;

    rgru_kernel<<<NCTA, NTHR>>>(x, h0, eps, Wz, bz, Wr, br,
                                Wtx, btx, Wth, bth, Wd, bd, out);
}

// round 9
// speedup vs baseline: 1.6011x; 1.0093x over previous
#include <cuda_runtime.h>
#include <cstdint>

#define NCTA 128
#define NTHR 512

constexpr int B = 64, T = 1024, D = 256, H = 256;
constexpr int GROUPS = 8;
constexpr int P = 16;              // CTAs per group
constexpr int BG = 8;              // batches per group
constexpr int CPC = 16;            // columns per CTA (1 per warp)

__device__ unsigned g_arr[GROUPS][4][32];   // monotonic CTA-arrival counters
__device__ unsigned g_genv[GROUPS][4][32];  // generation words
__device__ unsigned g_abort = 0;
__device__ float g_hb[B * H];

// ---------------- helpers ----------------
__device__ __forceinline__ uint64_t packf2(float lo, float hi) {
    uint64_t d; asm("mov.b64 %0, {%1, %2};" : "=l"(d) : "f"(lo), "f"(hi)); return d;
}
__device__ __forceinline__ float2 unpackf2(uint64_t v) {
    float2 r; asm("mov.b64 {%0, %1}, %2;" : "=f"(r.x), "=f"(r.y) : "l"(v)); return r;
}
__device__ __forceinline__ uint64_t fma2(uint64_t a, uint64_t b, uint64_t c) {
    uint64_t d;
    asm("fma.rn.f32x2 %0, %1, %2, %3;" : "=l"(d) : "l"(a), "l"(b), "l"(c));
    return d;
}
__device__ __forceinline__ float sigmoid_fast(float x) {
    return __fdividef(1.0f, 1.0f + __expf(-x));
}
__device__ __forceinline__ float tanh_fast(float x) {
    float e = __expf(2.0f * x);
    return 1.0f - __fdividef(2.0f, e + 1.0f);
}

__global__ void __launch_bounds__(NTHR, 1) rgru_kernel(
    const float* __restrict__ x, const float* __restrict__ h0,
    const float* __restrict__ eps,
    const float* __restrict__ Wz, const float* __restrict__ bz,
    const float* __restrict__ Wr, const float* __restrict__ br,
    const float* __restrict__ Wtx, const float* __restrict__ btx,
    const float* __restrict__ Wth, const float* __restrict__ bth,
    const float* __restrict__ Wd, const float* __restrict__ bd,
    float* __restrict__ out)
{
    __shared__ unsigned swc[4];   // per-CTA warp-arrival counters (monotonic)
    __shared__ unsigned sbs[4];   // generation snapshot

    const int tid = threadIdx.x;
    const int l = tid & 31;
    const int w = tid >> 5;            // warp 0..15 -> 1 column
    const int g = blockIdx.x >> 4;
    const int p = blockIdx.x & 15;
    const int Jb = p * CPC;
    const int Bb = g * BG;
    const int j = Jb + w;              // this warp's column

    if (tid < 4) {
        swc[tid] = 0u;
        sbs[tid] = *(volatile unsigned*)&g_genv[g][tid][0];
    }
    __syncthreads();                   // the ONLY block-wide sync
    const unsigned sb0 = sbs[0], sb1 = sbs[1], sb2 = sbs[2], sb3 = sbs[3];

    // ---------------- packed weights into registers (once) ----------------
    uint64_t wz2[8], wr2[8], wu2[4], wv2[4], wm2[4], wlv2[4];
#pragma unroll
    for (int q = 0; q < 4; q++)
#pragma unroll
        for (int i = 0; i < 2; i++) {
            int k0 = 128 * q + 4 * l + 2 * i;
            wz2[2 * q + i] = packf2(Wz[k0 * H + j], Wz[(k0 + 1) * H + j]);
            wr2[2 * q + i] = packf2(Wr[k0 * H + j], Wr[(k0 + 1) * H + j]);
        }
#pragma unroll
    for (int q = 0; q < 2; q++)
#pragma unroll
        for (int i = 0; i < 2; i++) {
            int k0 = 128 * q + 4 * l + 2 * i;
            wu2[2 * q + i]  = packf2(Wtx[k0 * H + j], Wtx[(k0 + 1) * H + j]);
            wv2[2 * q + i]  = packf2(Wth[k0 * H + j], Wth[(k0 + 1) * H + j]);
            wm2[2 * q + i]  = packf2(Wd[k0 * 2 * H + j], Wd[(k0 + 1) * 2 * H + j]);
            wlv2[2 * q + i] = packf2(Wd[k0 * 2 * H + j + H], Wd[(k0 + 1) * 2 * H + j + H]);
        }
    const float bzj = bz[j], brj = br[j], btxj = btx[j], bthj = bth[j];
    const float bmj = bd[j], blj = bd[j + H];

    // per-warp hierarchical arrive: smem count -> CTA global count -> gen
    auto arrive = [&](int id, unsigned tgt) {
        __threadfence();
        if (l == 0) {
            unsigned o = atomicAdd(&swc[id], 1u);
            if (((o + 1u) & 15u) == 0u) {            // last warp of CTA
                unsigned go = atomicAdd(&g_arr[g][id][0], 1u);
                if (((go + 1u) % (unsigned)P) == 0u) // last CTA of group
                    atomicExch(&g_genv[g][id][0], tgt);
            }
        }
    };
    // per-warp tight poll (bounded: aborts after ~2e9 cyc so GPU can't hang)
    auto waitg = [&](int id, unsigned tgt) {
        volatile unsigned* pp = &g_genv[g][id][0];
        if ((int)(*pp - tgt) < 0) {
            long long t0 = clock64();
            while ((int)(*pp - tgt) < 0) {
                if (*(volatile unsigned*)&g_abort) return;
                if (clock64() - t0 > 2000000000LL) { atomicExch(&g_abort, 1u); return; }
            }
        }
        __threadfence();
    };

    // phase 1: z, r, htil -> g_hb   (half = 4 batches starting at bbase)
    auto phase1 = [&](int bbase, int t) {
        float fin = 0.f;
        const int pb = Bb + bbase + (l & 3);
        const float* hrow_t = (t == 0) ? (h0 + pb * H)
                                       : (out + ((size_t)pb * T + (t - 1)) * H);
        float hpsel = __ldcg(hrow_t + j);
#pragma unroll
        for (int bb = 0; bb < 4; bb++) {
            const int b = Bb + bbase + bb;
            const float* xrow = x + ((size_t)b * T + t) * D;
            const float* hrow = (t == 0) ? (h0 + b * H)
                                         : (out + ((size_t)b * T + (t - 1)) * H);
            float4 xv0 = __ldg((const float4*)xrow + l);
            float4 xv1 = __ldg((const float4*)xrow + 32 + l);
            float4 hv0 = __ldcg((const float4*)hrow + l);
            float4 hv1 = __ldcg((const float4*)hrow + 32 + l);
            uint64_t a2[8] = { packf2(xv0.x, xv0.y), packf2(xv0.z, xv0.w),
                               packf2(xv1.x, xv1.y), packf2(xv1.z, xv1.w),
                               packf2(hv0.x, hv0.y), packf2(hv0.z, hv0.w),
                               packf2(hv1.x, hv1.y), packf2(hv1.z, hv1.w) };
            uint64_t sz2 = 0, sr2 = 0, su2 = 0, sv2 = 0;
#pragma unroll
            for (int i = 0; i < 8; i++) {
                sz2 = fma2(wz2[i], a2[i], sz2);
                sr2 = fma2(wr2[i], a2[i], sr2);
            }
#pragma unroll
            for (int i = 0; i < 4; i++) {
                su2 = fma2(wu2[i], a2[i], su2);
                sv2 = fma2(wv2[i], a2[4 + i], sv2);
            }
            float2 f;
            f = unpackf2(sz2); float sz = f.x + f.y;
            f = unpackf2(sr2); float sr = f.x + f.y;
            f = unpackf2(su2); float su = f.x + f.y;
            f = unpackf2(sv2); float sv = f.x + f.y;
            // 6-shfl 4-value reduction: z->lanes0-7, r->8-15, u->16-23, v->24-31
            const bool hi16 = (l & 16) != 0;
            float sA = hi16 ? sz : su;
            float rA = __shfl_xor_sync(0xffffffffu, sA, 16);
            float zu = hi16 ? (su + rA) : (sz + rA);
            float sB = hi16 ? sr : sv;
            float rB = __shfl_xor_sync(0xffffffffu, sB, 16);
            float rv = hi16 ? (sv + rB) : (sr + rB);
            const bool hi8 = (l & 8) != 0;
            float sC = hi8 ? zu : rv;
            float rC = __shfl_xor_sync(0xffffffffu, sC, 8);
            float myv = hi8 ? (rv + rC) : (zu + rC);
            myv += __shfl_xor_sync(0xffffffffu, myv, 4);
            myv += __shfl_xor_sync(0xffffffffu, myv, 2);
            myv += __shfl_xor_sync(0xffffffffu, myv, 1);
            fin = ((l & 7) == bb) ? myv : fin;
        }
        const int tb = l & 3;
        float zs = __shfl_sync(0xffffffffu, fin, tb);
        float rs = __shfl_sync(0xffffffffu, fin, tb + 8);
        float us = __shfl_sync(0xffffffffu, fin, tb + 16);
        float vs = __shfl_sync(0xffffffffu, fin, tb + 24);
        float z  = sigmoid_fast(zs + bzj);
        float r  = sigmoid_fast(rs + brj);
        float th = tanh_fast(us + btxj + r * (vs + bthj));
        float hbv = fmaf(z, hpsel - th, th);         // z*hp + (1-z)*th
        if (l < 4) g_hb[(Bb + bbase + tb) * H + j] = hbv;
    };

    // phase 2: mean/log_var -> sample(out)
    auto phase2 = [&](int bbase, int t) {
        float fin = 0.f;
#pragma unroll
        for (int bb = 0; bb < 4; bb++) {
            const float* hbrow = g_hb + (Bb + bbase + bb) * H;
            float4 q0 = __ldcg((const float4*)hbrow + l);
            float4 q1 = __ldcg((const float4*)hbrow + 32 + l);
            uint64_t h2[4] = { packf2(q0.x, q0.y), packf2(q0.z, q0.w),
                               packf2(q1.x, q1.y), packf2(q1.z, q1.w) };
            uint64_t sm2 = 0, sl2 = 0;
#pragma unroll
            for (int i = 0; i < 4; i++) {
                sm2 = fma2(wm2[i], h2[i], sm2);
                sl2 = fma2(wlv2[i], h2[i], sl2);
            }
            float2 f;
            f = unpackf2(sm2); float sm = f.x + f.y;
            f = unpackf2(sl2); float sl = f.x + f.y;
            // 5-shfl 2-value reduction: m->lanes0-15, lv->16-31
            const bool hi16 = (l & 16) != 0;
            float sA = hi16 ? sm : sl;
            float rA = __shfl_xor_sync(0xffffffffu, sA, 16);
            float mv = hi16 ? (sl + rA) : (sm + rA);
            mv += __shfl_xor_sync(0xffffffffu, mv, 8);
            mv += __shfl_xor_sync(0xffffffffu, mv, 4);
            mv += __shfl_xor_sync(0xffffffffu, mv, 2);
            mv += __shfl_xor_sync(0xffffffffu, mv, 1);
            fin = ((l & 15) == bb) ? mv : fin;
        }
        const int tb = l & 3;
        float ms = __shfl_sync(0xffffffffu, fin, tb);
        float ls = __shfl_sync(0xffffffffu, fin, tb + 16);
        float mean = fminf(fmaxf(ms + bmj, -1000.0f), 1000.0f);
        float lv   = fminf(fmaxf(ls + blj, -30.0f), 30.0f);
        float ep   = __ldg(eps + ((size_t)(Bb + bbase + tb) * T + t) * H + j);
        float s    = fmaf(__expf(0.5f * lv), ep, mean);
        if (l < 4) {
            int b = Bb + bbase + tb;
            out[((size_t)b * T + t) * H + j] = s;
            if (t == T - 1) out[(size_t)B * T * H + b * H + j] = s;
        }
    };

    // ---------------- main loop: per-warp pipeline, no block syncs ----------
    for (int t = 0; t < T; t++) {
        const unsigned tp1 = (unsigned)(t + 1);

        if (t > 0) waitg(2, sb2 + (unsigned)t);   // out(t-1) rows 0..3 visible
        phase1(0, t);
        arrive(0, sb0 + tp1);

        if (t > 0) waitg(3, sb3 + (unsigned)t);   // out(t-1) rows 4..7 visible
        phase1(4, t);
        arrive(1, sb1 + tp1);

        waitg(0, sb0 + tp1);                      // h_base rows 0..3 visible
        phase2(0, t);
        arrive(2, sb2 + tp1);

        waitg(1, sb1 + tp1);                      // h_base rows 4..7 visible
        phase2(4, t);
        arrive(3, sb3 + tp1);
    }
}

extern "C" void kernel_launch(void* const* d_in, const int* in_sizes, int n_in,
                              void* d_out, int out_size) {
    const float* x   = (const float*)d_in[0];
    const float* h0  = (const float*)d_in[1];
    const float* eps = (const float*)d_in[2];
    const float* Wz  = (const float*)d_in[3];
    const float* bz  = (const float*)d_in[4];
    const float* Wr  = (const float*)d_in[5];
    const float* br  = (const float*)d_in[6];
    const float* Wtx = (const float*)d_in[7];
    const float* btx = (const float*)d_in[8];
    const float* Wth = (const float*)d_in[9];
    const float* bth = (const float*)d_in[10];
    const float* Wd  = (const float*)d_in[11];
    const float* bd  = (const float*)d_in[12];
    float* out = (float*)d_out;

    rgru_kernel<<<NCTA, NTHR>>>(x, h0, eps, Wz, bz, Wr, br,
                                Wtx, btx, Wth, bth, Wd, bd, out);
}